// round 10
// baseline (speedup 1.0000x reference)
#include <cuda_runtime.h>
#include <cuda_bf16.h>
#include <math.h>
#include <stdint.h>

#define NN      50048      // padded node count (391 * 128)
#define NREAL   50000
#define NE      300000
#define KD      256
#define HID     256
#define NSTEP   8
#define SCANB   ((NN + 1023) / 1024)   // 49

// ---------------- scratch (static device globals; no runtime alloc) ----------
__device__ float g_h [NN * HID];
__device__ __nv_bfloat16 g_hHa[NN * KD], g_hLa[NN * KD];
__device__ __nv_bfloat16 g_hHb[NN * KD], g_hLb[NN * KD];
__device__ __nv_bfloat16 g_xH[NN * KD],  g_xL[NN * KD];
__device__ __nv_bfloat16 g_aggH[NN * KD], g_aggL[NN * KD];
__device__ __nv_bfloat16 g_WcatH[NSTEP * 1024 * 512], g_WcatL[NSTEP * 1024 * 512];
__device__ __nv_bfloat16 g_WredH[256 * KD], g_WredL[256 * KD];
__device__ __nv_bfloat16 g_WihH[768 * KD], g_WihL[768 * KD];
__device__ __nv_bfloat16 g_WgH[NSTEP * 256 * 256], g_WgL[NSTEP * 256 * 256];
__device__ float g_cb4[1024];
__device__ int g_cnt[NN], g_rowptr[NN + 1], g_cur[NN], g_eidx[NE];
__device__ int g_bsum[SCANB], g_boff[SCANB];

// ---------------- shared GEMM machinery --------------------------------------
#define BK    32
#define SA    40                       // smem row stride in bf16 elems (80B)
#define PLANEB (128 * SA * 2)          // 10240 B (128-row plane)
#define STAGEB (4 * PLANEB)            // 40960 B  (init/wfus stage)
#define GSMEM  (2 * STAGEB)            // 81920 B
#define BPLANE (256 * SA * 2)          // 20480 B (256-row B plane, fused)
#define STG2   (2 * PLANEB + 2 * BPLANE)  // 61440 B per fused stage
#define GSMEM2 (3 * STG2)              // 184320 B

__device__ __forceinline__ void mma_bf16(float* c, const unsigned* a, const unsigned* b)
{
    asm volatile(
        "mma.sync.aligned.m16n8k16.row.col.f32.bf16.bf16.f32 "
        "{%0,%1,%2,%3}, {%4,%5,%6,%7}, {%8,%9}, {%0,%1,%2,%3};\n"
        : "+f"(c[0]), "+f"(c[1]), "+f"(c[2]), "+f"(c[3])
        : "r"(a[0]), "r"(a[1]), "r"(a[2]), "r"(a[3]), "r"(b[0]), "r"(b[1]));
}
__device__ __forceinline__ void ldsm4(unsigned* r, uint32_t addr)
{
    asm volatile("ldmatrix.sync.aligned.m8n8.x4.shared.b16 {%0,%1,%2,%3}, [%4];"
                 : "=r"(r[0]), "=r"(r[1]), "=r"(r[2]), "=r"(r[3]) : "r"(addr));
}
__device__ __forceinline__ void cpasync16(char* dst, const void* src)
{
    asm volatile("cp.async.cg.shared.global [%0], [%1], 16;"
                 :: "l"((uint64_t)__cvta_generic_to_shared(dst)), "l"(src) : "memory");
}

// dead < 0: no skip. dead in {4,6}: skip that ni2 (ldsm + mma).
#define GEMM_COMPUTE(base, BHOFF, BLOFF, dead)                                 \
    do {                                                                       \
        _Pragma("unroll")                                                      \
        for (int ks = 0; ks < 2; ks++) {                                       \
            const uint32_t kso = ks * 32;                                      \
            unsigned aH[2][4], aL[2][4];                                       \
            ldsm4(aH[0], (base) + 0 * PLANEB + aoffH0 + kso);                  \
            ldsm4(aH[1], (base) + 0 * PLANEB + aoffH1 + kso);                  \
            ldsm4(aL[0], (base) + 1 * PLANEB + aoffH0 + kso);                  \
            ldsm4(aL[1], (base) + 1 * PLANEB + aoffH1 + kso);                  \
            _Pragma("unroll")                                                  \
            for (int ni2 = 0; ni2 < 8; ni2 += 2) {                             \
                if ((dead) >= 0 && ni2 == (dead)) continue;                    \
                unsigned bH[4], bL[4];                                         \
                const uint32_t bo = boff0 + (uint32_t)(ni2 * 8 * SA * 2) + kso;\
                ldsm4(bH, (base) + (BHOFF) + bo);                              \
                ldsm4(bL, (base) + (BLOFF) + bo);                              \
                _Pragma("unroll")                                              \
                for (int mi = 0; mi < 2; mi++)                                 \
                    _Pragma("unroll")                                          \
                    for (int q = 0; q < 2; q++)                                \
                        mma_bf16(acc[mi][ni2 + q], aH[mi], bH + q * 2);        \
                _Pragma("unroll")                                              \
                for (int mi = 0; mi < 2; mi++)                                 \
                    _Pragma("unroll")                                          \
                    for (int q = 0; q < 2; q++)                                \
                        mma_bf16(acc[mi][ni2 + q], aH[mi], bL + q * 2);        \
                _Pragma("unroll")                                              \
                for (int mi = 0; mi < 2; mi++)                                 \
                    _Pragma("unroll")                                          \
                    for (int q = 0; q < 2; q++)                                \
                        mma_bf16(acc[mi][ni2 + q], aL[mi], bH + q * 2);        \
            }                                                                  \
        }                                                                      \
    } while (0)

#define FRAG_SETUP()                                                           \
    const int tid  = threadIdx.x;                                              \
    const int lane = tid & 31;                                                 \
    const int warp = tid >> 5;                                                 \
    const int wm   = warp & 3;                                                 \
    const int wn   = warp >> 2;                                                \
    const int g    = lane >> 2;                                                \
    const int tq   = lane & 3;                                                 \
    const int a_row = wm * 32 + (lane & 15);                                   \
    const int a_kx  = (lane >> 4) * 16;                                        \
    const uint32_t aoffH0 = (uint32_t)(a_row * SA * 2 + a_kx);                 \
    const uint32_t aoffH1 = aoffH0 + 16 * SA * 2;                              \
    const int b_col = wn * 64 + (lane & 7) + ((lane >> 4) & 1) * 8;            \
    const int b_kx  = ((lane >> 3) & 1) * 16;                                  \
    const uint32_t boff0 = (uint32_t)(b_col * SA * 2 + b_kx)

#define ACC_INIT()                                                             \
    float acc[2][8][4];                                                        \
    _Pragma("unroll")                                                          \
    for (int mi = 0; mi < 2; mi++)                                             \
        _Pragma("unroll")                                                      \
        for (int ni = 0; ni < 8; ni++)                                         \
            _Pragma("unroll")                                                  \
            for (int j = 0; j < 4; j++) acc[mi][ni][j] = 0.0f

__device__ __forceinline__ void split1(float v, __nv_bfloat16& h, __nv_bfloat16& l) {
    h = __float2bfloat16(v);
    l = __float2bfloat16(v - __bfloat162float(h));
}
__device__ __forceinline__ float sigf(float x) { return 1.0f / (1.0f + __expf(-x)); }

// ---------------- init GEMM: C = A@B^T + bias (256 thr, 2-stage) -------------
__global__ void __launch_bounds__(256, 2)
gemm_init(const __nv_bfloat16* __restrict__ AH, const __nv_bfloat16* __restrict__ AL,
          const __nv_bfloat16* __restrict__ BH, const __nv_bfloat16* __restrict__ BL,
          const float* __restrict__ bias, float* __restrict__ C, int ldc)
{
    extern __shared__ char sm[];
    const uint32_t sb = (uint32_t)__cvta_generic_to_shared(sm);
    FRAG_SETUP();
    const int row0 = blockIdx.y * 128, col0 = blockIdx.x * 128;
    const __nv_bfloat16* gp[4] = {AH, AL, BH, BL};

    auto copy_stage = [&](int st, int kc) {
        const int k0 = kc * BK;
        char* dst0 = sm + st * STAGEB;
#pragma unroll
        for (int i = 0; i < 8; i++) {
            const int idx = i * 256 + tid;
            const int p = idx >> 9, r = (idx >> 2) & 127, j = idx & 3;
            const int grow = ((p < 2) ? row0 : col0) + r;
            cpasync16(dst0 + p * PLANEB + r * (SA * 2) + j * 16,
                      gp[p] + (size_t)grow * KD + k0 + j * 8);
        }
        asm volatile("cp.async.commit_group;" ::: "memory");
    };

    ACC_INIT();
    copy_stage(0, 0);
    const int NCHUNK = KD / BK;
    for (int c = 0; c < NCHUNK; c++) {
        const int st = c & 1;
        if (c + 1 < NCHUNK) { copy_stage(st ^ 1, c + 1);
            asm volatile("cp.async.wait_group 1;" ::: "memory");
        } else asm volatile("cp.async.wait_group 0;" ::: "memory");
        __syncthreads();
        GEMM_COMPUTE(sb + st * STAGEB, 2 * PLANEB, 3 * PLANEB, -1);
        __syncthreads();
    }
#pragma unroll
    for (int mi = 0; mi < 2; mi++) {
        const int r = row0 + wm * 32 + mi * 16 + g;
#pragma unroll
        for (int ni = 0; ni < 8; ni++) {
            const int cc = col0 + wn * 64 + ni * 8 + tq * 2;
            const float b0 = bias[cc], b1 = bias[cc + 1];
            *(float2*)(C + (size_t)r * ldc + cc) =
                make_float2(acc[mi][ni][0] + b0, acc[mi][ni][1] + b1);
            *(float2*)(C + (size_t)(r + 8) * ldc + cc) =
                make_float2(acc[mi][ni][2] + b0, acc[mi][ni][3] + b1);
        }
    }
}

// ---------------- Wfused GEMM: Wfus[t] = Wih @ Wg_t^T -> Wcat K-lo -----------
// grid (2, 6, 8): col0 = bx*128 (k of Wf), row0 = by*128 (o 0..767), t = bz.
__global__ void __launch_bounds__(256, 2)
gemm_wfus(const __nv_bfloat16* __restrict__ AH, const __nv_bfloat16* __restrict__ AL,
          const __nv_bfloat16* __restrict__ BHall, const __nv_bfloat16* __restrict__ BLall,
          __nv_bfloat16* __restrict__ catH, __nv_bfloat16* __restrict__ catL)
{
    extern __shared__ char sm[];
    const uint32_t sb = (uint32_t)__cvta_generic_to_shared(sm);
    FRAG_SETUP();
    const int row0 = blockIdx.y * 128, col0 = blockIdx.x * 128;
    const int t = blockIdx.z;
    const __nv_bfloat16* gp[4] = {AH, AL, BHall + (size_t)t * 65536,
                                  BLall + (size_t)t * 65536};

    auto copy_stage = [&](int st, int kc) {
        const int k0 = kc * BK;
        char* dst0 = sm + st * STAGEB;
#pragma unroll
        for (int i = 0; i < 8; i++) {
            const int idx = i * 256 + tid;
            const int p = idx >> 9, r = (idx >> 2) & 127, j = idx & 3;
            const int grow = ((p < 2) ? row0 : col0) + r;
            cpasync16(dst0 + p * PLANEB + r * (SA * 2) + j * 16,
                      gp[p] + (size_t)grow * 256 + k0 + j * 8);
        }
        asm volatile("cp.async.commit_group;" ::: "memory");
    };

    ACC_INIT();
    copy_stage(0, 0);
    for (int c = 0; c < 8; c++) {
        const int st = c & 1;
        if (c + 1 < 8) { copy_stage(st ^ 1, c + 1);
            asm volatile("cp.async.wait_group 1;" ::: "memory");
        } else asm volatile("cp.async.wait_group 0;" ::: "memory");
        __syncthreads();
        GEMM_COMPUTE(sb + st * STAGEB, 2 * PLANEB, 3 * PLANEB, -1);
        __syncthreads();
    }
    const size_t tcat = (size_t)t * 1024 * 512;
#pragma unroll
    for (int mi = 0; mi < 2; mi++) {
        const int r = row0 + wm * 32 + mi * 16 + g;
#pragma unroll
        for (int ni = 0; ni < 8; ni++) {
            const int cc = col0 + wn * 64 + ni * 8 + tq * 2;
#pragma unroll
            for (int j = 0; j < 4; j++) {
                const int o  = (j < 2) ? r : r + 8;
                const int kk = cc + (j & 1);
                const int gate = o >> 8, hh = o & 255;
                const int R = ((hh >> 6) << 8) | (((hh >> 4) & 3) << 6)
                            | (gate << 4) | (hh & 15);
                __nv_bfloat16 hv, lv;
                split1(acc[mi][ni][j], hv, lv);
                catH[tcat + (size_t)R * 512 + kk] = hv;
                catL[tcat + (size_t)R * 512 + kk] = lv;
            }
        }
    }
}

// ---------------- fused step GEMM + GRU --------------------------------------
// grid (4, NN/128), 512 threads, 3-stage pipeline.
// Tile: 128 rows x 256 cols; cols = wn*64 + gate*16 + c (4 gates per warp).
__global__ void __launch_bounds__(512, 1)
gemm_gru(const __nv_bfloat16* __restrict__ aggH, const __nv_bfloat16* __restrict__ aggL,
         const __nv_bfloat16* __restrict__ hInH, const __nv_bfloat16* __restrict__ hInL,
         const __nv_bfloat16* __restrict__ WcH,  const __nv_bfloat16* __restrict__ WcL,
         const float* __restrict__ cb4, float* __restrict__ h,
         __nv_bfloat16* __restrict__ outH, __nv_bfloat16* __restrict__ outL)
{
    extern __shared__ char sm[];
    const uint32_t sb = (uint32_t)__cvta_generic_to_shared(sm);
    FRAG_SETUP();   // 16 warps: wm 0..3, wn 0..3
    const int row0 = blockIdx.y * 128;
    const int bx   = blockIdx.x;
    const size_t bR = (size_t)bx * 256;

    auto copy_stage = [&](int st, int kc) {
        const int k0 = kc * BK;
        const bool klo = kc < 8;
        const __nv_bfloat16* aP0 = klo ? aggH : hInH;
        const __nv_bfloat16* aP1 = klo ? aggL : hInL;
        const int ka = klo ? k0 : k0 - 256;
        char* dst0 = sm + st * STG2;
#pragma unroll
        for (int i = 0; i < 6; i++) {
            const int idx = i * 512 + tid;
            const int rw = idx >> 2, j = idx & 3;
            if (rw < 256) {
                const int p = rw >> 7, r = rw & 127;
                const __nv_bfloat16* ap = p ? aP1 : aP0;
                cpasync16(dst0 + p * PLANEB + r * (SA * 2) + j * 16,
                          ap + (size_t)(row0 + r) * KD + ka + j * 8);
            } else {
                const int rb = rw - 256;
                const int p = rb >> 8, r = rb & 255;
                const int gate = (r >> 4) & 3;
                if ((klo && gate == 3) || (!klo && gate == 2)) continue;
                const __nv_bfloat16* wp = p ? WcL : WcH;
                cpasync16(dst0 + 2 * PLANEB + p * BPLANE + r * (SA * 2) + j * 16,
                          wp + (bR + r) * 512 + k0 + j * 8);
            }
        }
        asm volatile("cp.async.commit_group;" ::: "memory");
    };

    ACC_INIT();
    copy_stage(0, 0);
    copy_stage(1, 1);
    for (int c = 0; c < 16; c++) {
        if (c < 15) asm volatile("cp.async.wait_group 1;" ::: "memory");
        else        asm volatile("cp.async.wait_group 0;" ::: "memory");
        __syncthreads();
        const uint32_t base = sb + (uint32_t)((c % 3) * STG2);
        const int dead = (c < 8) ? 6 : 4;
        GEMM_COMPUTE(base, 2 * PLANEB, 2 * PLANEB + BPLANE, dead);
        if (c + 2 < 16) copy_stage((c + 2) % 3, c + 2);
    }

    // ---- GRU epilogue: acc[mi][2g+j] holds gate g; same (row,hid) per thread
    const float* cbr = cb4;
    const float* cbz = cb4 + 256;
    const float* cbi = cb4 + 512;
    const float* cbn = cb4 + 768;
    const int hidb = bx * 64 + wn * 16;
#pragma unroll
    for (int mi = 0; mi < 2; mi++) {
#pragma unroll
        for (int half = 0; half < 2; half++) {
            const int row = row0 + wm * 32 + mi * 16 + g + half * 8;
#pragma unroll
            for (int j = 0; j < 2; j++) {
                const int hid = hidb + j * 8 + tq * 2;
                float o2[2];
#pragma unroll
                for (int e = 0; e < 2; e++) {
                    const int i4 = half * 2 + e;
                    const float rv = sigf(acc[mi][0 + j][i4] + cbr[hid + e]);
                    const float zv = sigf(acc[mi][2 + j][i4] + cbz[hid + e]);
                    const float nv = tanhf(acc[mi][4 + j][i4] + cbi[hid + e]
                                     + rv * (acc[mi][6 + j][i4] + cbn[hid + e]));
                    const float ho = h[(size_t)row * HID + hid + e];
                    o2[e] = (1.0f - zv) * nv + zv * ho;
                }
                *(float2*)(h + (size_t)row * HID + hid) = make_float2(o2[0], o2[1]);
                __nv_bfloat16 h0, l0, h1, l1;
                split1(o2[0], h0, l0);
                split1(o2[1], h1, l1);
                *(__nv_bfloat162*)(outH + (size_t)row * KD + hid) = __nv_bfloat162(h0, h1);
                *(__nv_bfloat162*)(outL + (size_t)row * KD + hid) = __nv_bfloat162(l0, l1);
            }
        }
    }
}

// ---------------- prep kernels -----------------------------------------------
__global__ void prep_x(const float* __restrict__ x,
                       __nv_bfloat16* __restrict__ xh, __nv_bfloat16* __restrict__ xl) {
    const int idx = blockIdx.x * 256 + threadIdx.x;
    if (idx >= NN * KD) return;
    const int row = idx >> 8, col = idx & 255;
    const float v = (row < NREAL && col < 200) ? x[row * 200 + col] : 0.0f;
    split1(v, xh[idx], xl[idx]);
}
__global__ void prep_wred(const float* __restrict__ W,
                          __nv_bfloat16* __restrict__ wh, __nv_bfloat16* __restrict__ wl) {
    const int idx = blockIdx.x * 256 + threadIdx.x;
    if (idx >= 256 * KD) return;
    const int n = idx >> 8, k = idx & 255;
    const float v = (k < 200) ? W[n * 200 + k] : 0.0f;
    split1(v, wh[idx], wl[idx]);
}
__global__ void prep_split(const float* __restrict__ W, int n,
                           __nv_bfloat16* __restrict__ wh, __nv_bfloat16* __restrict__ wl) {
    const int idx = blockIdx.x * 256 + threadIdx.x;
    if (idx >= n) return;
    split1(W[idx], wh[idx], wl[idx]);
}
// W_hh -> Wcat K-hi (for all t): rows gate {0,1,2->3}, k 256..511
__global__ void prep_whh_cat(const float* __restrict__ Whh,
                             __nv_bfloat16* __restrict__ catH,
                             __nv_bfloat16* __restrict__ catL) {
    const int idx = blockIdx.x * 256 + threadIdx.x;
    if (idx >= 768 * 256) return;
    const int o = idx >> 8, kk = idx & 255;
    const int gate = o >> 8, hh = o & 255;
    const int gmap = (gate == 2) ? 3 : gate;
    const int R = ((hh >> 6) << 8) | (((hh >> 4) & 3) << 6) | (gmap << 4) | (hh & 15);
    __nv_bfloat16 hv, lv;
    split1(Whh[idx], hv, lv);
    const int t = blockIdx.y;
    const size_t off = (size_t)t * 1024 * 512 + (size_t)R * 512 + 256 + kk;
    catH[off] = hv;
    catL[off] = lv;
}
__global__ void prep_cb4(const float* __restrict__ bih, const float* __restrict__ bhh,
                         float* __restrict__ cb) {
    const int c = blockIdx.x * 256 + threadIdx.x;
    if (c >= 1024) return;
    const int gate = c >> 8, i = c & 255;
    float v;
    if (gate == 0)      v = bih[i] + bhh[i];
    else if (gate == 1) v = bih[256 + i] + bhh[256 + i];
    else if (gate == 2) v = bih[512 + i];
    else                v = bhh[512 + i];
    cb[c] = v;
}
__global__ void split_h(const float* __restrict__ h,
                        __nv_bfloat16* __restrict__ hh, __nv_bfloat16* __restrict__ hl) {
    const int idx = blockIdx.x * 256 + threadIdx.x;
    if (idx >= NN * HID) return;
    split1(h[idx], hh[idx], hl[idx]);
}

// ---------------- CSR build (parallel 3-phase scan) --------------------------
__global__ void hist_kernel(const int* __restrict__ ei, int* __restrict__ cnt) {
    const int e = blockIdx.x * 256 + threadIdx.x;
    if (e >= NE) return;
    atomicAdd(&cnt[ei[NE + e]], 1);
}
__global__ void scan_local(const int* __restrict__ cnt, int* __restrict__ rowptr,
                           int* __restrict__ bsum) {
    __shared__ int s[1024];
    const int tid = threadIdx.x;
    const int idx = blockIdx.x * 1024 + tid;
    int v = (idx < NN) ? cnt[idx] : 0;
    s[tid] = v;
    __syncthreads();
#pragma unroll
    for (int off = 1; off < 1024; off <<= 1) {
        int t = (tid >= off) ? s[tid - off] : 0;
        __syncthreads();
        s[tid] += t;
        __syncthreads();
    }
    if (idx < NN) rowptr[idx + 1] = s[tid];
    if (tid == 1023) bsum[blockIdx.x] = s[1023];
}
__global__ void scan_bsum(const int* __restrict__ bsum, int* __restrict__ boff) {
    if (threadIdx.x == 0) {
        int acc = 0;
        for (int i = 0; i < SCANB; i++) { boff[i] = acc; acc += bsum[i]; }
    }
}
__global__ void scan_add(int* __restrict__ rowptr, const int* __restrict__ boff) {
    const int idx = blockIdx.x * 1024 + threadIdx.x;
    if (idx == 0) rowptr[0] = 0;
    if (idx < NN) rowptr[idx + 1] += boff[blockIdx.x];
}
__global__ void copycur_kernel(const int* __restrict__ rowptr, int* __restrict__ cur) {
    const int i = blockIdx.x * 256 + threadIdx.x;
    if (i < NN) cur[i] = rowptr[i];
}
__global__ void fill_kernel(const int* __restrict__ ei, int* __restrict__ cur,
                            int* __restrict__ eidx) {
    const int e = blockIdx.x * 256 + threadIdx.x;
    if (e >= NE) return;
    const int pos = atomicAdd(&cur[ei[NE + e]], 1);
    eidx[pos] = ei[e];
}

// ---------------- aggregation: warp/dst-node gather of h -> bf16 planes ------
__global__ void agg_kernel(const float* __restrict__ h,
                           const int* __restrict__ rowptr, const int* __restrict__ eidx,
                           __nv_bfloat16* __restrict__ aggH, __nv_bfloat16* __restrict__ aggL)
{
    const int w = (blockIdx.x * blockDim.x + threadIdx.x) >> 5;
    const int lane = threadIdx.x & 31;
    if (w >= NN) return;
    const int beg = rowptr[w], end = rowptr[w + 1];
    float4 a0 = make_float4(0, 0, 0, 0), a1 = make_float4(0, 0, 0, 0);
    for (int i = beg; i < end; i++) {
        const int s = eidx[i];
        const float4* hr = (const float4*)(h + (size_t)s * 256);
        const float4 v0 = hr[lane * 2], v1 = hr[lane * 2 + 1];
        a0.x += v0.x; a0.y += v0.y; a0.z += v0.z; a0.w += v0.w;
        a1.x += v1.x; a1.y += v1.y; a1.z += v1.z; a1.w += v1.w;
    }
    const float vals[8] = {a0.x, a0.y, a0.z, a0.w, a1.x, a1.y, a1.z, a1.w};
    unsigned hb[4], lb[4];
#pragma unroll
    for (int q = 0; q < 4; q++) {
        __nv_bfloat16 h0, l0, h1, l1;
        split1(vals[2 * q], h0, l0);
        split1(vals[2 * q + 1], h1, l1);
        __nv_bfloat162 ph(h0, h1), pl(l0, l1);
        hb[q] = *(unsigned*)&ph;
        lb[q] = *(unsigned*)&pl;
    }
    *(uint4*)(aggH + (size_t)w * 256 + lane * 8) = make_uint4(hb[0], hb[1], hb[2], hb[3]);
    *(uint4*)(aggL + (size_t)w * 256 + lane * 8) = make_uint4(lb[0], lb[1], lb[2], lb[3]);
}

// ---------------- head -------------------------------------------------------
__global__ void head_kernel(const float* __restrict__ h,
                            const float* __restrict__ W_lin,
                            const float* __restrict__ b_lin,
                            float* __restrict__ out, int N)
{
    const int gt = blockIdx.x * blockDim.x + threadIdx.x;
    const int node = gt >> 5;
    const int lane = gt & 31;
    if (node >= N) return;
    const float4* hr = (const float4*)(h + (size_t)node * HID);
    const float4* w0 = (const float4*)(W_lin);
    const float4* w1 = (const float4*)(W_lin + HID);
    float a0 = 0.0f, a1 = 0.0f;
#pragma unroll
    for (int it = 0; it < 2; it++) {
        const int i = lane + it * 32;
        float4 v = hr[i];
        v.x = fmaxf(v.x, 0.f); v.y = fmaxf(v.y, 0.f);
        v.z = fmaxf(v.z, 0.f); v.w = fmaxf(v.w, 0.f);
        const float4 x0 = w0[i], x1 = w1[i];
        a0 += v.x * x0.x + v.y * x0.y + v.z * x0.z + v.w * x0.w;
        a1 += v.x * x1.x + v.y * x1.y + v.z * x1.z + v.w * x1.w;
    }
#pragma unroll
    for (int off = 16; off > 0; off >>= 1) {
        a0 += __shfl_down_sync(0xffffffffu, a0, off);
        a1 += __shfl_down_sync(0xffffffffu, a1, off);
    }
    if (lane == 0) {
        const float o0 = a0 + b_lin[0];
        const float o1 = a1 + b_lin[1];
        const float mx = fmaxf(o0, o1);
        const float lse = mx + logf(expf(o0 - mx) + expf(o1 - mx));
        out[(size_t)node * 2 + 0] = o0 - lse;
        out[(size_t)node * 2 + 1] = o1 - lse;
    }
}

// ---------------- launch -----------------------------------------------------
extern "C" void kernel_launch(void* const* d_in, const int* in_sizes, int n_in,
                              void* d_out, int out_size)
{
    const float* x        = (const float*)d_in[0];
    const int*   ei       = (const int*)  d_in[1];
    const float* W_reduce = (const float*)d_in[3];
    const float* b_reduce = (const float*)d_in[4];
    const float* W_ggc    = (const float*)d_in[5];
    const float* W_ih     = (const float*)d_in[6];
    const float* W_hh     = (const float*)d_in[7];
    const float* b_ih     = (const float*)d_in[8];
    const float* b_hh     = (const float*)d_in[9];
    const float* W_lin    = (const float*)d_in[10];
    const float* b_lin    = (const float*)d_in[11];
    float* out = (float*)d_out;

    float *h, *cb4;
    __nv_bfloat16 *hHa, *hLa, *hHb, *hLb, *xH, *xL, *aggH, *aggL;
    __nv_bfloat16 *WcatH, *WcatL, *WrH, *WrL, *WiH, *WiL, *WgH, *WgL;
    int *cnt, *rowptr, *cur, *eidx, *bsum, *boff;
    cudaGetSymbolAddress((void**)&h, g_h);
    cudaGetSymbolAddress((void**)&cb4, g_cb4);
    cudaGetSymbolAddress((void**)&hHa, g_hHa);
    cudaGetSymbolAddress((void**)&hLa, g_hLa);
    cudaGetSymbolAddress((void**)&hHb, g_hHb);
    cudaGetSymbolAddress((void**)&hLb, g_hLb);
    cudaGetSymbolAddress((void**)&xH, g_xH);
    cudaGetSymbolAddress((void**)&xL, g_xL);
    cudaGetSymbolAddress((void**)&aggH, g_aggH);
    cudaGetSymbolAddress((void**)&aggL, g_aggL);
    cudaGetSymbolAddress((void**)&WcatH, g_WcatH);
    cudaGetSymbolAddress((void**)&WcatL, g_WcatL);
    cudaGetSymbolAddress((void**)&WrH, g_WredH);
    cudaGetSymbolAddress((void**)&WrL, g_WredL);
    cudaGetSymbolAddress((void**)&WiH, g_WihH);
    cudaGetSymbolAddress((void**)&WiL, g_WihL);
    cudaGetSymbolAddress((void**)&WgH, g_WgH);
    cudaGetSymbolAddress((void**)&WgL, g_WgL);
    cudaGetSymbolAddress((void**)&cnt, g_cnt);
    cudaGetSymbolAddress((void**)&rowptr, g_rowptr);
    cudaGetSymbolAddress((void**)&cur, g_cur);
    cudaGetSymbolAddress((void**)&eidx, g_eidx);
    cudaGetSymbolAddress((void**)&bsum, g_bsum);
    cudaGetSymbolAddress((void**)&boff, g_boff);

    cudaFuncSetAttribute(gemm_init, cudaFuncAttributeMaxDynamicSharedMemorySize, GSMEM);
    cudaFuncSetAttribute(gemm_wfus, cudaFuncAttributeMaxDynamicSharedMemorySize, GSMEM);
    cudaFuncSetAttribute(gemm_gru,  cudaFuncAttributeMaxDynamicSharedMemorySize, GSMEM2);

    // ---- preprocessing ----
    prep_x<<<(NN * KD + 255) / 256, 256>>>(x, xH, xL);
    prep_wred<<<(256 * KD + 255) / 256, 256>>>(W_reduce, WrH, WrL);
    prep_split<<<(768 * KD + 255) / 256, 256>>>(W_ih, 768 * KD, WiH, WiL);
    prep_split<<<(NSTEP * 65536 + 255) / 256, 256>>>(W_ggc, NSTEP * 65536, WgH, WgL);
    gemm_wfus<<<dim3(2, 6, NSTEP), 256, GSMEM>>>(WiH, WiL, WgH, WgL, WcatH, WcatL);
    prep_whh_cat<<<dim3((768 * 256 + 255) / 256, NSTEP), 256>>>(W_hh, WcatH, WcatL);
    prep_cb4<<<4, 256>>>(b_ih, b_hh, cb4);
    cudaMemsetAsync(cnt, 0, NN * sizeof(int));
    hist_kernel<<<(NE + 255) / 256, 256>>>(ei, cnt);
    scan_local<<<SCANB, 1024>>>(cnt, rowptr, bsum);
    scan_bsum<<<1, 32>>>(bsum, boff);
    scan_add<<<SCANB, 1024>>>(rowptr, boff);
    copycur_kernel<<<(NN + 255) / 256, 256>>>(rowptr, cur);
    fill_kernel<<<(NE + 255) / 256, 256>>>(ei, cur, eidx);

    const int MB = NN / 128;   // 391

    // h = x @ W_reduce^T + b_reduce
    gemm_init<<<dim3(2, MB), 256, GSMEM>>>(xH, xL, WrH, WrL, b_reduce, h, 256);
    split_h<<<(NN * HID + 255) / 256, 256>>>(h, hHa, hLa);

    __nv_bfloat16 *inH = hHa, *inL = hLa, *otH = hHb, *otL = hLb;
    for (int t = 0; t < NSTEP; t++) {
        agg_kernel<<<(NN * 32 + 255) / 256, 256>>>(h, rowptr, eidx, aggH, aggL);
        gemm_gru<<<dim3(4, MB), 512, GSMEM2>>>(
            aggH, aggL, inH, inL,
            WcatH + (size_t)t * 1024 * 512, WcatL + (size_t)t * 1024 * 512,
            cb4, h, otH, otL);
        __nv_bfloat16* tmp;
        tmp = inH; inH = otH; otH = tmp;
        tmp = inL; inL = otL; otL = tmp;
    }

    head_kernel<<<(NREAL * 32 + 255) / 256, 256>>>(h, W_lin, b_lin, out, NREAL);
}